// round 1
// baseline (speedup 1.0000x reference)
#include <cuda_runtime.h>
#include <cstdint>

#define Nn 16384
#define Ne 65536
#define Dd 64
#define Hh 128
#define Ll 3
#define Gg 512
#define Oo 128

// ---------------- scratch (static device allocations are the sanctioned path) ----
__device__ float g_x[Nn*Dd];                 // running node features
__device__ float g_h[Nn*Dd];                 // leaky(LN(x))
__device__ float g_y2[Nn*Dd];                // h @ B2 (b2 reshaped [D,D])
__device__ float g_a[(size_t)Ne*Hh];         // edge MLP hidden, 32 MB
__device__ float g_Q[(size_t)Nn*Hh*Dd];      // per-node factor, 512 MB
__device__ float g_num[Nn*Dd];               // message accumulator
__device__ float g_deg[Nn];
__device__ float g_pool[Gg*Dd];
__device__ float g_cnt[Gg];

__device__ __forceinline__ float leaky(float v){ return v > 0.f ? v : 0.01f*v; }

// packed f32x2 helpers (B300: required to reach full fp32 FMA rate)
__device__ __forceinline__ unsigned long long pk2(float lo, float hi){
    unsigned long long r; asm("mov.b64 %0,{%1,%2};" : "=l"(r) : "f"(lo), "f"(hi)); return r;
}
__device__ __forceinline__ void fma2(unsigned long long& c, unsigned long long a, unsigned long long b){
    asm("fma.rn.f32x2 %0, %1, %2, %0;" : "+l"(c) : "l"(a), "l"(b));
}
__device__ __forceinline__ float2 up2(unsigned long long v){
    float2 r; asm("mov.b64 {%0,%1},%2;" : "=f"(r.x), "=f"(r.y) : "l"(v)); return r;
}

// ---------------- init: copy x, zero accumulators -------------------------------
__global__ void k_init(const float* __restrict__ x){
    int i = blockIdx.x*blockDim.x + threadIdx.x;
    if(i < Nn*Dd){ g_x[i] = x[i]; g_num[i] = 0.f; }
    if(i < Gg*Dd) g_pool[i] = 0.f;
    if(i < Nn)    g_deg[i]  = 0.f;
    if(i < Gg)    g_cnt[i]  = 0.f;
}

__global__ void k_degcnt(const int* __restrict__ ei, const int* __restrict__ batch){
    int i = blockIdx.x*blockDim.x + threadIdx.x;
    if(i < Ne) atomicAdd(&g_deg[ei[Ne + i]], 1.f);
    if(i < Nn) atomicAdd(&g_cnt[batch[i]], 1.f);
}

// ---------------- h = leaky(LN(x)*scale+bias); one warp per row -----------------
__global__ void k_ln(const float* __restrict__ sc, const float* __restrict__ bi){
    int lane = threadIdx.x & 31, w = threadIdx.x >> 5;
    int n = blockIdx.x*8 + w;
    float v0 = g_x[n*64 + lane], v1 = g_x[n*64 + 32 + lane];
    float s = v0 + v1;
    #pragma unroll
    for(int o = 16; o; o >>= 1) s += __shfl_xor_sync(0xffffffffu, s, o);
    float mu = s * 0.015625f;
    float d0 = v0 - mu, d1 = v1 - mu;
    float q = d0*d0 + d1*d1;
    #pragma unroll
    for(int o = 16; o; o >>= 1) q += __shfl_xor_sync(0xffffffffu, q, o);
    float r = rsqrtf(q * 0.015625f + 1e-5f);
    g_h[n*64 + lane]      = leaky(d0*r*sc[lane]      + bi[lane]);
    g_h[n*64 + 32 + lane] = leaky(d1*r*sc[32 + lane] + bi[32 + lane]);
}

// ---------------- a = leaky(edge_attr @ W1 + b1)  [E,64]@[64,128] ----------------
__global__ __launch_bounds__(256) void k_emlp(const float* __restrict__ ea,
                                              const float* __restrict__ W1l,
                                              const float* __restrict__ b1l){
    __shared__ float As[64][64];   // edge_attr tile (row-major)
    __shared__ float Bs[64][128];  // W1[l]
    int tid = threadIdx.x;
    int e0 = blockIdx.x * 64;
    #pragma unroll
    for(int i = 0; i < 4; i++){
        int idx = i*256 + tid; int m = idx >> 4, d = (idx & 15) * 4;
        *(float4*)&As[m][d] = *(const float4*)&ea[(size_t)(e0 + m)*64 + d];
    }
    #pragma unroll
    for(int i = 0; i < 8; i++){
        int idx = i*256 + tid; int d = idx >> 5, f = (idx & 31) * 4;
        *(float4*)&Bs[d][f] = *(const float4*)&W1l[d*128 + f];
    }
    __syncthreads();
    int tx = tid & 15, ty = tid >> 4;  // TN=8 cols, TM=4 rows
    float acc[4][8];
    #pragma unroll
    for(int i = 0; i < 4; i++)
        #pragma unroll
        for(int j = 0; j < 8; j++) acc[i][j] = 0.f;

    #pragma unroll 4
    for(int d4 = 0; d4 < 64; d4 += 4){
        float4 a[4];
        #pragma unroll
        for(int i = 0; i < 4; i++) a[i] = *(float4*)&As[ty*4 + i][d4];
        #pragma unroll
        for(int dd = 0; dd < 4; dd++){
            float4 b0 = *(float4*)&Bs[d4 + dd][tx*8];
            float4 b1 = *(float4*)&Bs[d4 + dd][tx*8 + 4];
            #pragma unroll
            for(int i = 0; i < 4; i++){
                float av = (dd==0)?a[i].x:(dd==1)?a[i].y:(dd==2)?a[i].z:a[i].w;
                acc[i][0] = fmaf(av, b0.x, acc[i][0]);
                acc[i][1] = fmaf(av, b0.y, acc[i][1]);
                acc[i][2] = fmaf(av, b0.z, acc[i][2]);
                acc[i][3] = fmaf(av, b0.w, acc[i][3]);
                acc[i][4] = fmaf(av, b1.x, acc[i][4]);
                acc[i][5] = fmaf(av, b1.y, acc[i][5]);
                acc[i][6] = fmaf(av, b1.z, acc[i][6]);
                acc[i][7] = fmaf(av, b1.w, acc[i][7]);
            }
        }
    }
    float bias[8];
    #pragma unroll
    for(int j = 0; j < 8; j++) bias[j] = b1l[tx*8 + j];
    #pragma unroll
    for(int i = 0; i < 4; i++){
        float4 o0, o1;
        o0.x = leaky(acc[i][0]+bias[0]); o0.y = leaky(acc[i][1]+bias[1]);
        o0.z = leaky(acc[i][2]+bias[2]); o0.w = leaky(acc[i][3]+bias[3]);
        o1.x = leaky(acc[i][4]+bias[4]); o1.y = leaky(acc[i][5]+bias[5]);
        o1.z = leaky(acc[i][6]+bias[6]); o1.w = leaky(acc[i][7]+bias[7]);
        size_t base = (size_t)(e0 + ty*4 + i)*128 + tx*8;
        *(float4*)&g_a[base]     = o0;
        *(float4*)&g_a[base + 4] = o1;
    }
}

// ---------------- Q[n,k,f] = sum_d h[n,d] * W2[l,k,d,f]  (dominant GEMM) ---------
// grid (N/128, H); CTA: 128 nodes x 64 f for one k; f32x2 packed FMA.
__global__ __launch_bounds__(256) void k_q(const float* __restrict__ W2l){
    __shared__ float Hs[128][64];
    __shared__ float Bs[64][64];
    int tid = threadIdx.x;
    int k  = blockIdx.y;
    int n0 = blockIdx.x * 128;
    #pragma unroll
    for(int i = 0; i < 8; i++){
        int idx = i*256 + tid; int m = idx >> 4, d = (idx & 15) * 4;
        *(float4*)&Hs[m][d] = *(const float4*)&g_h[(size_t)(n0 + m)*64 + d];
    }
    const float* B = W2l + (size_t)k * 4096;
    #pragma unroll
    for(int i = 0; i < 4; i++){
        int idx = i*256 + tid; int d = idx >> 4, f = (idx & 15) * 4;
        *(float4*)&Bs[d][f] = *(const float4*)&B[d*64 + f];
    }
    __syncthreads();
    int tx = tid & 15, ty = tid >> 4;   // TN=4 (2 packed pairs), TM=8
    unsigned long long acc[8][2];
    #pragma unroll
    for(int i = 0; i < 8; i++){ acc[i][0] = 0ull; acc[i][1] = 0ull; }

    #pragma unroll 4
    for(int d4 = 0; d4 < 64; d4 += 4){
        float4 a[8];
        #pragma unroll
        for(int i = 0; i < 8; i++) a[i] = *(float4*)&Hs[ty*8 + i][d4];
        #pragma unroll
        for(int dd = 0; dd < 4; dd++){
            float4 bv = *(float4*)&Bs[d4 + dd][tx*4];
            unsigned long long b0 = pk2(bv.x, bv.y), b1 = pk2(bv.z, bv.w);
            #pragma unroll
            for(int i = 0; i < 8; i++){
                float av = (dd==0)?a[i].x:(dd==1)?a[i].y:(dd==2)?a[i].z:a[i].w;
                unsigned long long a2 = pk2(av, av);
                fma2(acc[i][0], a2, b0);
                fma2(acc[i][1], a2, b1);
            }
        }
    }
    #pragma unroll
    for(int i = 0; i < 8; i++){
        float2 lo = up2(acc[i][0]), hi = up2(acc[i][1]);
        float4 o; o.x = lo.x; o.y = lo.y; o.z = hi.x; o.w = hi.y;
        int n = n0 + ty*8 + i;
        *(float4*)&g_Q[((size_t)n*128 + k)*64 + tx*4] = o;
    }
}

// ---------------- per-edge: msg = y2[src] + a[e] . Q[src]; scatter-add to dst ----
__global__ __launch_bounds__(256) void k_msg(const int* __restrict__ ei){
    __shared__ float as[4][128];
    int tid = threadIdx.x;
    int e0 = blockIdx.x * 4;
    #pragma unroll
    for(int i = 0; i < 2; i++){
        int idx = i*256 + tid; int e = idx >> 7, k = idx & 127;
        as[e][k] = g_a[(size_t)(e0 + e)*128 + k];
    }
    __syncthreads();
    int eg = tid >> 6, f = tid & 63;
    int e = e0 + eg;
    int src = ei[e], dst = ei[Ne + e];
    const float* q = g_Q + (size_t)src * 8192 + f;
    float acc = g_y2[src*64 + f];
    #pragma unroll 8
    for(int k = 0; k < 128; k++)
        acc = fmaf(as[eg][k], __ldg(&q[(size_t)k * 64]), acc);
    atomicAdd(&g_num[dst*64 + f], acc);
}

// ---------------- shared 64x64 small GEMM with three epilogues -------------------
// mode 0: g_y2 = g_h @ B
// mode 1: g_x += g_num/max(deg,1) + g_h @ B + cb;  g_num = 0
// mode 2: pool[batch] += g_x @ B + bias  (atomic)
__global__ __launch_bounds__(256) void k_nn64(const float* __restrict__ B,
                                              const float* __restrict__ bias,
                                              const float* __restrict__ cb,
                                              const int* __restrict__ batch,
                                              int mode){
    __shared__ float As[64][64];
    __shared__ float Bs[64][64];
    const float* A = (mode == 2) ? g_x : g_h;
    int tid = threadIdx.x;
    int n0 = blockIdx.x * 64;
    #pragma unroll
    for(int i = 0; i < 4; i++){
        int idx = i*256 + tid; int m = idx >> 4, d = (idx & 15) * 4;
        *(float4*)&As[m][d] = *(const float4*)&A[(size_t)(n0 + m)*64 + d];
        *(float4*)&Bs[m][d] = *(const float4*)&B[(size_t)m*64 + d];
    }
    __syncthreads();
    int tx = tid & 15, ty = tid >> 4;
    float acc[4][4];
    #pragma unroll
    for(int i = 0; i < 4; i++)
        #pragma unroll
        for(int j = 0; j < 4; j++) acc[i][j] = 0.f;

    #pragma unroll 4
    for(int d4 = 0; d4 < 64; d4 += 4){
        float4 a[4];
        #pragma unroll
        for(int i = 0; i < 4; i++) a[i] = *(float4*)&As[ty*4 + i][d4];
        #pragma unroll
        for(int dd = 0; dd < 4; dd++){
            float4 bv = *(float4*)&Bs[d4 + dd][tx*4];
            #pragma unroll
            for(int i = 0; i < 4; i++){
                float av = (dd==0)?a[i].x:(dd==1)?a[i].y:(dd==2)?a[i].z:a[i].w;
                acc[i][0] = fmaf(av, bv.x, acc[i][0]);
                acc[i][1] = fmaf(av, bv.y, acc[i][1]);
                acc[i][2] = fmaf(av, bv.z, acc[i][2]);
                acc[i][3] = fmaf(av, bv.w, acc[i][3]);
            }
        }
    }
    if(mode == 0){
        #pragma unroll
        for(int i = 0; i < 4; i++){
            float4 o; o.x = acc[i][0]; o.y = acc[i][1]; o.z = acc[i][2]; o.w = acc[i][3];
            *(float4*)&g_y2[(size_t)(n0 + ty*4 + i)*64 + tx*4] = o;
        }
    } else if(mode == 1){
        #pragma unroll
        for(int i = 0; i < 4; i++){
            int n = n0 + ty*4 + i;
            float inv = 1.f / fmaxf(g_deg[n], 1.f);
            #pragma unroll
            for(int j = 0; j < 4; j++){
                int idx = n*64 + tx*4 + j;
                float v = g_x[idx] + g_num[idx]*inv + acc[i][j] + cb[tx*4 + j];
                g_x[idx] = v;
                g_num[idx] = 0.f;   // ready for next layer
            }
        }
    } else {
        #pragma unroll
        for(int i = 0; i < 4; i++){
            int n = n0 + ty*4 + i;
            int b = batch[n];
            #pragma unroll
            for(int j = 0; j < 4; j++)
                atomicAdd(&g_pool[b*64 + tx*4 + j], acc[i][j] + bias[tx*4 + j]);
        }
    }
}

// ---------------- head: out[g] = leaky(pool/cnt) @ out_W + out_b -----------------
__global__ void k_out(const float* __restrict__ oW, const float* __restrict__ ob,
                      float* __restrict__ out){
    __shared__ float p[64];
    int g = blockIdx.x, t = threadIdx.x;
    if(t < 64){
        float c = fmaxf(g_cnt[g], 1.f);
        p[t] = leaky(g_pool[g*64 + t] / c);
    }
    __syncthreads();
    float acc = ob[t];
    #pragma unroll 8
    for(int f = 0; f < 64; f++)
        acc = fmaf(p[f], oW[f*128 + t], acc);
    out[g*128 + t] = acc;
}

// ---------------- launch ----------------------------------------------------------
extern "C" void kernel_launch(void* const* d_in, const int* in_sizes, int n_in,
                              void* d_out, int out_size){
    const float* x    = (const float*)d_in[0];
    const int*   ei   = (const int*)  d_in[1];
    const float* ea   = (const float*)d_in[2];
    const int*   batch= (const int*)  d_in[3];
    const float* lns  = (const float*)d_in[4];
    const float* lnb  = (const float*)d_in[5];
    const float* W1   = (const float*)d_in[6];
    const float* b1   = (const float*)d_in[7];
    const float* W2   = (const float*)d_in[8];
    const float* b2   = (const float*)d_in[9];
    const float* root = (const float*)d_in[10];
    const float* cb   = (const float*)d_in[11];
    const float* dW   = (const float*)d_in[12];
    const float* db   = (const float*)d_in[13];
    const float* oW   = (const float*)d_in[14];
    const float* ob   = (const float*)d_in[15];
    float* out = (float*)d_out;

    k_init<<<(Nn*Dd + 255)/256, 256>>>(x);
    k_degcnt<<<(Ne + 255)/256, 256>>>(ei, batch);

    for(int l = 0; l < Ll; l++){
        k_ln<<<Nn/8, 256>>>(lns + l*64, lnb + l*64);
        k_emlp<<<Ne/64, 256>>>(ea, W1 + (size_t)l*64*128, b1 + (size_t)l*128);
        k_nn64<<<Nn/64, 256>>>(b2 + (size_t)l*4096, nullptr, nullptr, nullptr, 0); // y2 = h@B2
        dim3 gq(Nn/128, Hh);
        k_q<<<gq, 256>>>(W2 + (size_t)l*Hh*4096);
        k_msg<<<Ne/4, 256>>>(ei);
        k_nn64<<<Nn/64, 256>>>(root + (size_t)l*4096, nullptr, cb + (size_t)l*64, nullptr, 1);
    }

    k_nn64<<<Nn/64, 256>>>(dW, db, nullptr, batch, 2);  // dense + pool
    k_out<<<Gg, 128>>>(oW, ob, out);
}

// round 4
// speedup vs baseline: 1.2542x; 1.2542x over previous
#include <cuda_runtime.h>
#include <cuda_bf16.h>
#include <cstdint>

#define Nn 16384
#define Ne 65536
#define Dd 64
#define Hh 128
#define Ll 3
#define Gg 512
#define Oo 128

// ---------------- scratch -------------------------------------------------------
__device__ float g_x[Nn*Dd];
__device__ float g_h[Nn*Dd];
__device__ float g_y2[Nn*Dd];
__device__ float g_a[(size_t)Ne*Hh];
__device__ float g_Q[(size_t)Nn*Hh*Dd];          // [n][k][f], 512 MB
__device__ float g_num[Nn*Dd];
__device__ float g_deg[Nn];
__device__ float g_pool[Gg*Dd];
__device__ float g_cnt[Gg];
// CSR by src
__device__ int g_srccnt[Nn];
__device__ int g_cursor[Nn];
__device__ int g_rowptr[Nn + 1];
__device__ int g_edst[Ne];
__device__ int g_eidx[Ne];

__device__ __forceinline__ float leaky(float v){ return v > 0.f ? v : 0.01f*v; }

// packed f32x2 helpers (B300: required to reach full fp32 FMA rate)
__device__ __forceinline__ unsigned long long pk2(float lo, float hi){
    unsigned long long r; asm("mov.b64 %0,{%1,%2};" : "=l"(r) : "f"(lo), "f"(hi)); return r;
}
__device__ __forceinline__ void fma2(unsigned long long& c, unsigned long long a, unsigned long long b){
    asm("fma.rn.f32x2 %0, %1, %2, %0;" : "+l"(c) : "l"(a), "l"(b));
}
__device__ __forceinline__ float2 up2(unsigned long long v){
    float2 r; asm("mov.b64 {%0,%1},%2;" : "=f"(r.x), "=f"(r.y) : "l"(v)); return r;
}

// ---------------- init -----------------------------------------------------------
__global__ void k_init(const float* __restrict__ x){
    int i = blockIdx.x*blockDim.x + threadIdx.x;
    if(i < Nn*Dd){ g_x[i] = x[i]; g_num[i] = 0.f; }
    if(i < Gg*Dd) g_pool[i] = 0.f;
    if(i < Nn){ g_deg[i] = 0.f; g_srccnt[i] = 0; g_cursor[i] = 0; }
    if(i < Gg)  g_cnt[i] = 0.f;
}

__global__ void k_degcnt(const int* __restrict__ ei, const int* __restrict__ batch){
    int i = blockIdx.x*blockDim.x + threadIdx.x;
    if(i < Ne){
        atomicAdd(&g_deg[ei[Ne + i]], 1.f);
        atomicAdd(&g_srccnt[ei[i]], 1);
    }
    if(i < Nn) atomicAdd(&g_cnt[batch[i]], 1.f);
}

// single-block exclusive scan of g_srccnt -> g_rowptr
__global__ void k_scan(){
    __shared__ int wsum[32];
    int t = threadIdx.x;                    // 1024 threads, 16 each
    int base = t*16;
    int c[16]; int s = 0;
    #pragma unroll
    for(int i = 0; i < 16; i++){ c[i] = g_srccnt[base + i]; s += c[i]; }
    int lane = t & 31, w = t >> 5;
    int v = s;
    #pragma unroll
    for(int o = 1; o < 32; o <<= 1){ int u = __shfl_up_sync(~0u, v, o); if(lane >= o) v += u; }
    if(lane == 31) wsum[w] = v;
    __syncthreads();
    if(w == 0){
        int x = wsum[lane];
        #pragma unroll
        for(int o = 1; o < 32; o <<= 1){ int u = __shfl_up_sync(~0u, x, o); if(lane >= o) x += u; }
        wsum[lane] = x;
    }
    __syncthreads();
    int run = v - s + (w > 0 ? wsum[w-1] : 0);
    #pragma unroll
    for(int i = 0; i < 16; i++){ g_rowptr[base + i] = run; run += c[i]; }
    if(t == 1023) g_rowptr[Nn] = run;
}

__global__ void k_fill(const int* __restrict__ ei){
    int e = blockIdx.x*blockDim.x + threadIdx.x;
    if(e >= Ne) return;
    int src = ei[e];
    int pos = g_rowptr[src] + atomicAdd(&g_cursor[src], 1);
    g_edst[pos] = ei[Ne + e];
    g_eidx[pos] = e;
}

// ---------------- h = leaky(LN(x)*scale+bias); one warp per row -----------------
__global__ void k_ln(const float* __restrict__ sc, const float* __restrict__ bi){
    int lane = threadIdx.x & 31, w = threadIdx.x >> 5;
    int n = blockIdx.x*8 + w;
    float v0 = g_x[n*64 + lane], v1 = g_x[n*64 + 32 + lane];
    float s = v0 + v1;
    #pragma unroll
    for(int o = 16; o; o >>= 1) s += __shfl_xor_sync(0xffffffffu, s, o);
    float mu = s * 0.015625f;
    float d0 = v0 - mu, d1 = v1 - mu;
    float q = d0*d0 + d1*d1;
    #pragma unroll
    for(int o = 16; o; o >>= 1) q += __shfl_xor_sync(0xffffffffu, q, o);
    float r = rsqrtf(q * 0.015625f + 1e-5f);
    g_h[n*64 + lane]      = leaky(d0*r*sc[lane]      + bi[lane]);
    g_h[n*64 + 32 + lane] = leaky(d1*r*sc[32 + lane] + bi[32 + lane]);
}

// ---------------- a = leaky(edge_attr @ W1 + b1)  [E,64]@[64,128] ----------------
__global__ __launch_bounds__(256) void k_emlp(const float* __restrict__ ea,
                                              const float* __restrict__ W1l,
                                              const float* __restrict__ b1l){
    __shared__ float As[64][64];   // edge_attr tile (row-major)
    __shared__ float Bs[64][128];  // W1[l]
    int tid = threadIdx.x;
    int e0 = blockIdx.x * 64;
    #pragma unroll
    for(int i = 0; i < 4; i++){
        int idx = i*256 + tid; int m = idx >> 4, d = (idx & 15) * 4;
        *(float4*)&As[m][d] = *(const float4*)&ea[(size_t)(e0 + m)*64 + d];
    }
    #pragma unroll
    for(int i = 0; i < 8; i++){
        int idx = i*256 + tid; int d = idx >> 5, f = (idx & 31) * 4;
        *(float4*)&Bs[d][f] = *(const float4*)&W1l[d*128 + f];
    }
    __syncthreads();
    int tx = tid & 15, ty = tid >> 4;  // TN=8 cols, TM=4 rows
    float acc[4][8];
    #pragma unroll
    for(int i = 0; i < 4; i++)
        #pragma unroll
        for(int j = 0; j < 8; j++) acc[i][j] = 0.f;

    #pragma unroll 4
    for(int d4 = 0; d4 < 64; d4 += 4){
        float4 a[4];
        #pragma unroll
        for(int i = 0; i < 4; i++) a[i] = *(float4*)&As[ty*4 + i][d4];
        #pragma unroll
        for(int dd = 0; dd < 4; dd++){
            float4 b0 = *(float4*)&Bs[d4 + dd][tx*8];
            float4 b1 = *(float4*)&Bs[d4 + dd][tx*8 + 4];
            #pragma unroll
            for(int i = 0; i < 4; i++){
                float av = (dd==0)?a[i].x:(dd==1)?a[i].y:(dd==2)?a[i].z:a[i].w;
                acc[i][0] = fmaf(av, b0.x, acc[i][0]);
                acc[i][1] = fmaf(av, b0.y, acc[i][1]);
                acc[i][2] = fmaf(av, b0.z, acc[i][2]);
                acc[i][3] = fmaf(av, b0.w, acc[i][3]);
                acc[i][4] = fmaf(av, b1.x, acc[i][4]);
                acc[i][5] = fmaf(av, b1.y, acc[i][5]);
                acc[i][6] = fmaf(av, b1.z, acc[i][6]);
                acc[i][7] = fmaf(av, b1.w, acc[i][7]);
            }
        }
    }
    float bias[8];
    #pragma unroll
    for(int j = 0; j < 8; j++) bias[j] = b1l[tx*8 + j];
    #pragma unroll
    for(int i = 0; i < 4; i++){
        float4 o0, o1;
        o0.x = leaky(acc[i][0]+bias[0]); o0.y = leaky(acc[i][1]+bias[1]);
        o0.z = leaky(acc[i][2]+bias[2]); o0.w = leaky(acc[i][3]+bias[3]);
        o1.x = leaky(acc[i][4]+bias[4]); o1.y = leaky(acc[i][5]+bias[5]);
        o1.z = leaky(acc[i][6]+bias[6]); o1.w = leaky(acc[i][7]+bias[7]);
        size_t base = (size_t)(e0 + ty*4 + i)*128 + tx*8;
        *(float4*)&g_a[base]     = o0;
        *(float4*)&g_a[base + 4] = o1;
    }
}

// ---------------- Q[n,k,f] = sum_d h[n,d] * W2[l,k,d,f]  (FFMA, proven R1) -------
__global__ __launch_bounds__(256) void k_q(const float* __restrict__ W2l){
    __shared__ float Hs[128][64];
    __shared__ float Bs[64][64];
    int tid = threadIdx.x;
    int k  = blockIdx.y;
    int n0 = blockIdx.x * 128;
    #pragma unroll
    for(int i = 0; i < 8; i++){
        int idx = i*256 + tid; int m = idx >> 4, d = (idx & 15) * 4;
        *(float4*)&Hs[m][d] = *(const float4*)&g_h[(size_t)(n0 + m)*64 + d];
    }
    const float* B = W2l + (size_t)k * 4096;
    #pragma unroll
    for(int i = 0; i < 4; i++){
        int idx = i*256 + tid; int d = idx >> 4, f = (idx & 15) * 4;
        *(float4*)&Bs[d][f] = *(const float4*)&B[d*64 + f];
    }
    __syncthreads();
    int tx = tid & 15, ty = tid >> 4;   // TN=4 (2 packed pairs), TM=8
    unsigned long long acc[8][2];
    #pragma unroll
    for(int i = 0; i < 8; i++){ acc[i][0] = 0ull; acc[i][1] = 0ull; }

    #pragma unroll 4
    for(int d4 = 0; d4 < 64; d4 += 4){
        float4 a[8];
        #pragma unroll
        for(int i = 0; i < 8; i++) a[i] = *(float4*)&Hs[ty*8 + i][d4];
        #pragma unroll
        for(int dd = 0; dd < 4; dd++){
            float4 bv = *(float4*)&Bs[d4 + dd][tx*4];
            unsigned long long b0 = pk2(bv.x, bv.y), b1 = pk2(bv.z, bv.w);
            #pragma unroll
            for(int i = 0; i < 8; i++){
                float av = (dd==0)?a[i].x:(dd==1)?a[i].y:(dd==2)?a[i].z:a[i].w;
                unsigned long long a2 = pk2(av, av);
                fma2(acc[i][0], a2, b0);
                fma2(acc[i][1], a2, b1);
            }
        }
    }
    #pragma unroll
    for(int i = 0; i < 8; i++){
        float2 lo = up2(acc[i][0]), hi = up2(acc[i][1]);
        float4 o; o.x = lo.x; o.y = lo.y; o.z = hi.x; o.w = hi.y;
        int n = n0 + ty*8 + i;
        *(float4*)&g_Q[((size_t)n*128 + k)*64 + tx*4] = o;
    }
}

// ---------------- messages: block per src node, Q[n] staged in smem ----------------
__global__ __launch_bounds__(256) void k_msg2(){
    __shared__ float Qs[128*64];
    __shared__ float as[4][128];
    __shared__ float y2s[64];
    int n = blockIdx.x;
    int beg = g_rowptr[n], end = g_rowptr[n+1];
    if(beg == end) return;
    int tid = threadIdx.x;
    const float4* qsrc = (const float4*)(g_Q + (size_t)n*8192);
    float4* qd = (float4*)Qs;
    #pragma unroll
    for(int i = 0; i < 8; i++) qd[i*256 + tid] = qsrc[i*256 + tid];
    if(tid < 64) y2s[tid] = g_y2[n*64 + tid];
    __syncthreads();
    int g = tid >> 6, f = tid & 63;
    for(int base = beg; base < end; base += 4){
        int j = base + g;
        int dst = 0;
        bool act = (j < end);
        if(act){
            dst = g_edst[j];
            int eid = g_eidx[j];
            as[g][f]      = g_a[(size_t)eid*128 + f];
            as[g][64 + f] = g_a[(size_t)eid*128 + 64 + f];
        }
        __syncthreads();
        if(act){
            float acc = y2s[f];
            #pragma unroll 16
            for(int k = 0; k < 128; k++)
                acc = fmaf(as[g][k], Qs[k*64 + f], acc);
            atomicAdd(&g_num[dst*64 + f], acc);
        }
        __syncthreads();
    }
}

// ---------------- shared 64x64 small GEMM with three epilogues -------------------
// mode 0: g_y2 = g_h @ B
// mode 1: g_x += g_num/max(deg,1) + g_h @ B + cb;  g_num = 0
// mode 2: pool[batch] += g_x @ B + bias  (atomic)
__global__ __launch_bounds__(256) void k_nn64(const float* __restrict__ B,
                                              const float* __restrict__ bias,
                                              const float* __restrict__ cb,
                                              const int* __restrict__ batch,
                                              int mode){
    __shared__ float As[64][64];
    __shared__ float Bs[64][64];
    const float* A = (mode == 2) ? g_x : g_h;
    int tid = threadIdx.x;
    int n0 = blockIdx.x * 64;
    #pragma unroll
    for(int i = 0; i < 4; i++){
        int idx = i*256 + tid; int m = idx >> 4, d = (idx & 15) * 4;
        *(float4*)&As[m][d] = *(const float4*)&A[(size_t)(n0 + m)*64 + d];
        *(float4*)&Bs[m][d] = *(const float4*)&B[(size_t)m*64 + d];
    }
    __syncthreads();
    int tx = tid & 15, ty = tid >> 4;
    float acc[4][4];
    #pragma unroll
    for(int i = 0; i < 4; i++)
        #pragma unroll
        for(int j = 0; j < 4; j++) acc[i][j] = 0.f;

    #pragma unroll 4
    for(int d4 = 0; d4 < 64; d4 += 4){
        float4 a[4];
        #pragma unroll
        for(int i = 0; i < 4; i++) a[i] = *(float4*)&As[ty*4 + i][d4];
        #pragma unroll
        for(int dd = 0; dd < 4; dd++){
            float4 bv = *(float4*)&Bs[d4 + dd][tx*4];
            #pragma unroll
            for(int i = 0; i < 4; i++){
                float av = (dd==0)?a[i].x:(dd==1)?a[i].y:(dd==2)?a[i].z:a[i].w;
                acc[i][0] = fmaf(av, bv.x, acc[i][0]);
                acc[i][1] = fmaf(av, bv.y, acc[i][1]);
                acc[i][2] = fmaf(av, bv.z, acc[i][2]);
                acc[i][3] = fmaf(av, bv.w, acc[i][3]);
            }
        }
    }
    if(mode == 0){
        #pragma unroll
        for(int i = 0; i < 4; i++){
            float4 o; o.x = acc[i][0]; o.y = acc[i][1]; o.z = acc[i][2]; o.w = acc[i][3];
            *(float4*)&g_y2[(size_t)(n0 + ty*4 + i)*64 + tx*4] = o;
        }
    } else if(mode == 1){
        #pragma unroll
        for(int i = 0; i < 4; i++){
            int n = n0 + ty*4 + i;
            float inv = 1.f / fmaxf(g_deg[n], 1.f);
            #pragma unroll
            for(int j = 0; j < 4; j++){
                int idx = n*64 + tx*4 + j;
                float v = g_x[idx] + g_num[idx]*inv + acc[i][j] + cb[tx*4 + j];
                g_x[idx] = v;
                g_num[idx] = 0.f;   // ready for next layer
            }
        }
    } else {
        #pragma unroll
        for(int i = 0; i < 4; i++){
            int n = n0 + ty*4 + i;
            int b = batch[n];
            #pragma unroll
            for(int j = 0; j < 4; j++)
                atomicAdd(&g_pool[b*64 + tx*4 + j], acc[i][j] + bias[tx*4 + j]);
        }
    }
}

// ---------------- head: out[g] = leaky(pool/cnt) @ out_W + out_b -----------------
__global__ void k_out(const float* __restrict__ oW, const float* __restrict__ ob,
                      float* __restrict__ out){
    __shared__ float p[64];
    int g = blockIdx.x, t = threadIdx.x;
    if(t < 64){
        float c = fmaxf(g_cnt[g], 1.f);
        p[t] = leaky(g_pool[g*64 + t] / c);
    }
    __syncthreads();
    float acc = ob[t];
    #pragma unroll 8
    for(int f = 0; f < 64; f++)
        acc = fmaf(p[f], oW[f*128 + t], acc);
    out[g*128 + t] = acc;
}

// ---------------- launch ----------------------------------------------------------
extern "C" void kernel_launch(void* const* d_in, const int* in_sizes, int n_in,
                              void* d_out, int out_size){
    const float* x    = (const float*)d_in[0];
    const int*   ei   = (const int*)  d_in[1];
    const float* ea   = (const float*)d_in[2];
    const int*   batch= (const int*)  d_in[3];
    const float* lns  = (const float*)d_in[4];
    const float* lnb  = (const float*)d_in[5];
    const float* W1   = (const float*)d_in[6];
    const float* b1   = (const float*)d_in[7];
    const float* W2   = (const float*)d_in[8];
    const float* b2   = (const float*)d_in[9];
    const float* root = (const float*)d_in[10];
    const float* cb   = (const float*)d_in[11];
    const float* dW   = (const float*)d_in[12];
    const float* db   = (const float*)d_in[13];
    const float* oW   = (const float*)d_in[14];
    const float* ob   = (const float*)d_in[15];
    float* out = (float*)d_out;

    k_init<<<(Nn*Dd + 255)/256, 256>>>(x);
    k_degcnt<<<(Ne + 255)/256, 256>>>(ei, batch);
    k_scan<<<1, 1024>>>();
    k_fill<<<(Ne + 255)/256, 256>>>(ei);

    for(int l = 0; l < Ll; l++){
        k_ln<<<Nn/8, 256>>>(lns + l*64, lnb + l*64);
        k_emlp<<<Ne/64, 256>>>(ea, W1 + (size_t)l*64*128, b1 + (size_t)l*128);
        k_nn64<<<Nn/64, 256>>>(b2 + (size_t)l*4096, nullptr, nullptr, nullptr, 0); // y2 = h@B2
        dim3 gq(Nn/128, Hh);
        k_q<<<gq, 256>>>(W2 + (size_t)l*Hh*4096);
        k_msg2<<<Nn, 256>>>();
        k_nn64<<<Nn/64, 256>>>(root + (size_t)l*4096, nullptr, cb + (size_t)l*64, nullptr, 1);
    }

    k_nn64<<<Nn/64, 256>>>(dW, db, nullptr, batch, 2);  // dense + pool
    k_out<<<Gg, 128>>>(oW, ob, out);
}

// round 5
// speedup vs baseline: 1.7068x; 1.3609x over previous
#include <cuda_runtime.h>
#include <cuda_bf16.h>
#include <cstdint>

#define Nn 16384
#define Ne 65536
#define Dd 64
#define Hh 128
#define Ll 3
#define Gg 512
#define Oo 128

// ---------------- scratch -------------------------------------------------------
__device__ float g_x[Nn*Dd];
__device__ float g_h[Nn*Dd];
__device__ __nv_bfloat16 g_h_hi[Nn*Dd];
__device__ __nv_bfloat16 g_h_lo[Nn*Dd];
__device__ float g_y2[Nn*Dd];
__device__ float g_a[(size_t)Ne*Hh];
__device__ float g_Q[(size_t)Nn*Hh*Dd];                  // [n][k][f], 512 MB
__device__ __nv_bfloat16 g_w2t_hi[(size_t)Ll*Hh*Dd*Dd]; // [l][k][f][d]
__device__ __nv_bfloat16 g_w2t_lo[(size_t)Ll*Hh*Dd*Dd];
__device__ float g_num[Nn*Dd];
__device__ float g_deg[Nn];
__device__ float g_pool[Gg*Dd];
__device__ float g_cnt[Gg];
// CSR by src
__device__ int g_srccnt[Nn];
__device__ int g_cursor[Nn];
__device__ int g_rowptr[Nn + 1];
__device__ int g_edst[Ne];
__device__ int g_eidx[Ne];

__device__ __forceinline__ float leaky(float v){ return v > 0.f ? v : 0.01f*v; }

// ---------------- init -----------------------------------------------------------
__global__ void k_init(const float* __restrict__ x){
    int i = blockIdx.x*blockDim.x + threadIdx.x;
    if(i < Nn*Dd){ g_x[i] = x[i]; g_num[i] = 0.f; }
    if(i < Gg*Dd) g_pool[i] = 0.f;
    if(i < Nn){ g_deg[i] = 0.f; g_srccnt[i] = 0; g_cursor[i] = 0; }
    if(i < Gg)  g_cnt[i] = 0.f;
}

__global__ void k_degcnt(const int* __restrict__ ei, const int* __restrict__ batch){
    int i = blockIdx.x*blockDim.x + threadIdx.x;
    if(i < Ne){
        atomicAdd(&g_deg[ei[Ne + i]], 1.f);
        atomicAdd(&g_srccnt[ei[i]], 1);
    }
    if(i < Nn) atomicAdd(&g_cnt[batch[i]], 1.f);
}

// single-block exclusive scan of g_srccnt -> g_rowptr
__global__ void k_scan(){
    __shared__ int wsum[32];
    int t = threadIdx.x;                    // 1024 threads, 16 each
    int base = t*16;
    int c[16]; int s = 0;
    #pragma unroll
    for(int i = 0; i < 16; i++){ c[i] = g_srccnt[base + i]; s += c[i]; }
    int lane = t & 31, w = t >> 5;
    int v = s;
    #pragma unroll
    for(int o = 1; o < 32; o <<= 1){ int u = __shfl_up_sync(~0u, v, o); if(lane >= o) v += u; }
    if(lane == 31) wsum[w] = v;
    __syncthreads();
    if(w == 0){
        int x = wsum[lane];
        #pragma unroll
        for(int o = 1; o < 32; o <<= 1){ int u = __shfl_up_sync(~0u, x, o); if(lane >= o) x += u; }
        wsum[lane] = x;
    }
    __syncthreads();
    int run = v - s + (w > 0 ? wsum[w-1] : 0);
    #pragma unroll
    for(int i = 0; i < 16; i++){ g_rowptr[base + i] = run; run += c[i]; }
    if(t == 1023) g_rowptr[Nn] = run;
}

__global__ void k_fill(const int* __restrict__ ei){
    int e = blockIdx.x*blockDim.x + threadIdx.x;
    if(e >= Ne) return;
    int src = ei[e];
    int pos = g_rowptr[src] + atomicAdd(&g_cursor[src], 1);
    g_edst[pos] = ei[Ne + e];
    g_eidx[pos] = e;
}

// ---------------- W2 transpose + bf16 split: [l][k][d][f] -> [l][k][f][d] ---------
__global__ void k_prep_w2(const float* __restrict__ W2){
    int idx = blockIdx.x*blockDim.x + threadIdx.x;   // coalesced on read
    if(idx >= Ll*Hh*Dd*Dd) return;
    int lk = idx >> 12;
    int d = (idx >> 6) & 63;
    int f = idx & 63;
    float v = W2[idx];
    __nv_bfloat16 hi = __float2bfloat16(v);
    __nv_bfloat16 lo = __float2bfloat16(v - __bfloat162float(hi));
    size_t o = (size_t)lk*4096 + f*64 + d;
    g_w2t_hi[o] = hi;
    g_w2t_lo[o] = lo;
}

// ---------------- h = leaky(LN(x)); also emit bf16 hi/lo --------------------------
__global__ void k_ln(const float* __restrict__ sc, const float* __restrict__ bi){
    int lane = threadIdx.x & 31, w = threadIdx.x >> 5;
    int n = blockIdx.x*8 + w;
    float v0 = g_x[n*64 + lane], v1 = g_x[n*64 + 32 + lane];
    float s = v0 + v1;
    #pragma unroll
    for(int o = 16; o; o >>= 1) s += __shfl_xor_sync(0xffffffffu, s, o);
    float mu = s * 0.015625f;
    float d0 = v0 - mu, d1 = v1 - mu;
    float q = d0*d0 + d1*d1;
    #pragma unroll
    for(int o = 16; o; o >>= 1) q += __shfl_xor_sync(0xffffffffu, q, o);
    float r = rsqrtf(q * 0.015625f + 1e-5f);
    float h0 = leaky(d0*r*sc[lane]      + bi[lane]);
    float h1 = leaky(d1*r*sc[32 + lane] + bi[32 + lane]);
    g_h[n*64 + lane]      = h0;
    g_h[n*64 + 32 + lane] = h1;
    __nv_bfloat16 h0h = __float2bfloat16(h0), h1h = __float2bfloat16(h1);
    g_h_hi[n*64 + lane]      = h0h;
    g_h_hi[n*64 + 32 + lane] = h1h;
    g_h_lo[n*64 + lane]      = __float2bfloat16(h0 - __bfloat162float(h0h));
    g_h_lo[n*64 + 32 + lane] = __float2bfloat16(h1 - __bfloat162float(h1h));
}

// ---------------- a = leaky(edge_attr @ W1 + b1)  [E,64]@[64,128] ----------------
__global__ __launch_bounds__(256) void k_emlp(const float* __restrict__ ea,
                                              const float* __restrict__ W1l,
                                              const float* __restrict__ b1l){
    __shared__ float As[64][64];
    __shared__ float Bs[64][128];
    int tid = threadIdx.x;
    int e0 = blockIdx.x * 64;
    #pragma unroll
    for(int i = 0; i < 4; i++){
        int idx = i*256 + tid; int m = idx >> 4, d = (idx & 15) * 4;
        *(float4*)&As[m][d] = *(const float4*)&ea[(size_t)(e0 + m)*64 + d];
    }
    #pragma unroll
    for(int i = 0; i < 8; i++){
        int idx = i*256 + tid; int d = idx >> 5, f = (idx & 31) * 4;
        *(float4*)&Bs[d][f] = *(const float4*)&W1l[d*128 + f];
    }
    __syncthreads();
    int tx = tid & 15, ty = tid >> 4;
    float acc[4][8];
    #pragma unroll
    for(int i = 0; i < 4; i++)
        #pragma unroll
        for(int j = 0; j < 8; j++) acc[i][j] = 0.f;

    #pragma unroll 4
    for(int d4 = 0; d4 < 64; d4 += 4){
        float4 a[4];
        #pragma unroll
        for(int i = 0; i < 4; i++) a[i] = *(float4*)&As[ty*4 + i][d4];
        #pragma unroll
        for(int dd = 0; dd < 4; dd++){
            float4 b0 = *(float4*)&Bs[d4 + dd][tx*8];
            float4 b1 = *(float4*)&Bs[d4 + dd][tx*8 + 4];
            #pragma unroll
            for(int i = 0; i < 4; i++){
                float av = (dd==0)?a[i].x:(dd==1)?a[i].y:(dd==2)?a[i].z:a[i].w;
                acc[i][0] = fmaf(av, b0.x, acc[i][0]);
                acc[i][1] = fmaf(av, b0.y, acc[i][1]);
                acc[i][2] = fmaf(av, b0.z, acc[i][2]);
                acc[i][3] = fmaf(av, b0.w, acc[i][3]);
                acc[i][4] = fmaf(av, b1.x, acc[i][4]);
                acc[i][5] = fmaf(av, b1.y, acc[i][5]);
                acc[i][6] = fmaf(av, b1.z, acc[i][6]);
                acc[i][7] = fmaf(av, b1.w, acc[i][7]);
            }
        }
    }
    float bias[8];
    #pragma unroll
    for(int j = 0; j < 8; j++) bias[j] = b1l[tx*8 + j];
    #pragma unroll
    for(int i = 0; i < 4; i++){
        float4 o0, o1;
        o0.x = leaky(acc[i][0]+bias[0]); o0.y = leaky(acc[i][1]+bias[1]);
        o0.z = leaky(acc[i][2]+bias[2]); o0.w = leaky(acc[i][3]+bias[3]);
        o1.x = leaky(acc[i][4]+bias[4]); o1.y = leaky(acc[i][5]+bias[5]);
        o1.z = leaky(acc[i][6]+bias[6]); o1.w = leaky(acc[i][7]+bias[7]);
        size_t base = (size_t)(e0 + ty*4 + i)*128 + tx*8;
        *(float4*)&g_a[base]     = o0;
        *(float4*)&g_a[base + 4] = o1;
    }
}

// ---------------- Q via mma.sync bf16 (3-term split, fp32 accum) -------------------
// Q[n,k,f] = sum_d h[n,d] * W2T[k,f,d].  A = h [128x64] row-major (regs),
// B = W2T[k] [64f x 64d] = col-major for row.col mma (smem, padded rows).
// Takes the LAYER INDEX (device-symbol offsets computed in device code — the R3
// version passed g_w2t_hi+off from host code, which is the host shadow symbol).
#define BPAD 72
__device__ __forceinline__ void mma_bf16(float* c, const uint32_t* a, uint32_t b0, uint32_t b1){
    asm volatile(
        "mma.sync.aligned.m16n8k16.row.col.f32.bf16.bf16.f32 "
        "{%0,%1,%2,%3}, {%4,%5,%6,%7}, {%8,%9}, {%0,%1,%2,%3};"
        : "+f"(c[0]), "+f"(c[1]), "+f"(c[2]), "+f"(c[3])
        : "r"(a[0]), "r"(a[1]), "r"(a[2]), "r"(a[3]), "r"(b0), "r"(b1));
}

__global__ __launch_bounds__(256) void k_q_mma(int layer){
    __shared__ __align__(16) __nv_bfloat16 Bh[64*BPAD];
    __shared__ __align__(16) __nv_bfloat16 Bl[64*BPAD];
    const __nv_bfloat16* w2h = g_w2t_hi + (size_t)layer*Hh*4096;
    const __nv_bfloat16* w2l = g_w2t_lo + (size_t)layer*Hh*4096;
    int tid = threadIdx.x, w = tid >> 5, lane = tid & 31;
    int g = lane >> 2, tq = lane & 3;
    int n0 = blockIdx.x * 128;
    int m0 = n0 + w*16;

    // A fragments for all 4 k-steps, hi and lo (register-resident)
    uint32_t ahi[4][4], alo[4][4];
    {
        const __nv_bfloat16* ph = g_h_hi;
        const __nv_bfloat16* pl = g_h_lo;
        int r0 = (m0 + g)*64, r1 = (m0 + g + 8)*64;
        #pragma unroll
        for(int ks = 0; ks < 4; ks++){
            int c0 = ks*16 + 2*tq, c1 = c0 + 8;
            ahi[ks][0] = *(const uint32_t*)&ph[r0 + c0];
            ahi[ks][1] = *(const uint32_t*)&ph[r1 + c0];
            ahi[ks][2] = *(const uint32_t*)&ph[r0 + c1];
            ahi[ks][3] = *(const uint32_t*)&ph[r1 + c1];
            alo[ks][0] = *(const uint32_t*)&pl[r0 + c0];
            alo[ks][1] = *(const uint32_t*)&pl[r1 + c0];
            alo[ks][2] = *(const uint32_t*)&pl[r0 + c1];
            alo[ks][3] = *(const uint32_t*)&pl[r1 + c1];
        }
    }

    for(int kk = 0; kk < 8; kk++){
        int k = blockIdx.y*8 + kk;
        // stage B hi/lo: 64 rows (f) x 64 (d) bf16, padded to BPAD
        {
            const uint4* sh = (const uint4*)(w2h + (size_t)k*4096);
            const uint4* sl = (const uint4*)(w2l + (size_t)k*4096);
            #pragma unroll
            for(int i = 0; i < 2; i++){
                int idx = i*256 + tid;          // 512 uint4 per matrix
                int f = idx >> 3, u = idx & 7;  // 8 x 16B per row
                *(uint4*)&Bh[f*BPAD + u*8] = sh[idx];
                *(uint4*)&Bl[f*BPAD + u*8] = sl[idx];
            }
        }
        __syncthreads();

        float acc[8][4];
        #pragma unroll
        for(int j = 0; j < 8; j++)
            #pragma unroll
            for(int i = 0; i < 4; i++) acc[j][i] = 0.f;

        #pragma unroll
        for(int ks = 0; ks < 4; ks++){
            int cb0 = ks*16 + 2*tq, cb1 = cb0 + 8;
            #pragma unroll
            for(int j = 0; j < 8; j++){
                int row = (j*8 + g)*BPAD;
                uint32_t bh0 = *(const uint32_t*)&Bh[row + cb0];
                uint32_t bh1 = *(const uint32_t*)&Bh[row + cb1];
                uint32_t bl0 = *(const uint32_t*)&Bl[row + cb0];
                uint32_t bl1 = *(const uint32_t*)&Bl[row + cb1];
                mma_bf16(acc[j], ahi[ks], bh0, bh1);   // hi*hi
                mma_bf16(acc[j], ahi[ks], bl0, bl1);   // hi*lo
                mma_bf16(acc[j], alo[ks], bh0, bh1);   // lo*hi
            }
        }

        // store D: rows m0+g / m0+g+8, cols j*8 + 2tq (+1)
        float* q0 = g_Q + ((size_t)(m0 + g)*128 + k)*64;
        float* q1 = g_Q + ((size_t)(m0 + g + 8)*128 + k)*64;
        #pragma unroll
        for(int j = 0; j < 8; j++){
            int c = j*8 + 2*tq;
            *(float2*)&q0[c] = make_float2(acc[j][0], acc[j][1]);
            *(float2*)&q1[c] = make_float2(acc[j][2], acc[j][3]);
        }
        __syncthreads();
    }
}

// ---------------- messages: block per src node, Q[n] staged in smem ----------------
__global__ __launch_bounds__(256) void k_msg2(){
    __shared__ float Qs[128*64];
    __shared__ float as[4][128];
    __shared__ float y2s[64];
    int n = blockIdx.x;
    int beg = g_rowptr[n], end = g_rowptr[n+1];
    if(beg == end) return;
    int tid = threadIdx.x;
    const float4* qsrc = (const float4*)(g_Q + (size_t)n*8192);
    float4* qd = (float4*)Qs;
    #pragma unroll
    for(int i = 0; i < 8; i++) qd[i*256 + tid] = qsrc[i*256 + tid];
    if(tid < 64) y2s[tid] = g_y2[n*64 + tid];
    __syncthreads();
    int g = tid >> 6, f = tid & 63;
    for(int base = beg; base < end; base += 4){
        int j = base + g;
        int dst = 0;
        bool act = (j < end);
        if(act){
            dst = g_edst[j];
            int eid = g_eidx[j];
            as[g][f]      = g_a[(size_t)eid*128 + f];
            as[g][64 + f] = g_a[(size_t)eid*128 + 64 + f];
        }
        __syncthreads();
        if(act){
            float acc = y2s[f];
            #pragma unroll 16
            for(int k = 0; k < 128; k++)
                acc = fmaf(as[g][k], Qs[k*64 + f], acc);
            atomicAdd(&g_num[dst*64 + f], acc);
        }
        __syncthreads();
    }
}

// ---------------- shared 64x64 small GEMM with three epilogues -------------------
__global__ __launch_bounds__(256) void k_nn64(const float* __restrict__ B,
                                              const float* __restrict__ bias,
                                              const float* __restrict__ cb,
                                              const int* __restrict__ batch,
                                              int mode){
    __shared__ float As[64][64];
    __shared__ float Bs[64][64];
    const float* A = (mode == 2) ? g_x : g_h;
    int tid = threadIdx.x;
    int n0 = blockIdx.x * 64;
    #pragma unroll
    for(int i = 0; i < 4; i++){
        int idx = i*256 + tid; int m = idx >> 4, d = (idx & 15) * 4;
        *(float4*)&As[m][d] = *(const float4*)&A[(size_t)(n0 + m)*64 + d];
        *(float4*)&Bs[m][d] = *(const float4*)&B[(size_t)m*64 + d];
    }
    __syncthreads();
    int tx = tid & 15, ty = tid >> 4;
    float acc[4][4];
    #pragma unroll
    for(int i = 0; i < 4; i++)
        #pragma unroll
        for(int j = 0; j < 4; j++) acc[i][j] = 0.f;

    #pragma unroll 4
    for(int d4 = 0; d4 < 64; d4 += 4){
        float4 a[4];
        #pragma unroll
        for(int i = 0; i < 4; i++) a[i] = *(float4*)&As[ty*4 + i][d4];
        #pragma unroll
        for(int dd = 0; dd < 4; dd++){
            float4 bv = *(float4*)&Bs[d4 + dd][tx*4];
            #pragma unroll
            for(int i = 0; i < 4; i++){
                float av = (dd==0)?a[i].x:(dd==1)?a[i].y:(dd==2)?a[i].z:a[i].w;
                acc[i][0] = fmaf(av, bv.x, acc[i][0]);
                acc[i][1] = fmaf(av, bv.y, acc[i][1]);
                acc[i][2] = fmaf(av, bv.z, acc[i][2]);
                acc[i][3] = fmaf(av, bv.w, acc[i][3]);
            }
        }
    }
    if(mode == 0){
        #pragma unroll
        for(int i = 0; i < 4; i++){
            float4 o; o.x = acc[i][0]; o.y = acc[i][1]; o.z = acc[i][2]; o.w = acc[i][3];
            *(float4*)&g_y2[(size_t)(n0 + ty*4 + i)*64 + tx*4] = o;
        }
    } else if(mode == 1){
        #pragma unroll
        for(int i = 0; i < 4; i++){
            int n = n0 + ty*4 + i;
            float inv = 1.f / fmaxf(g_deg[n], 1.f);
            #pragma unroll
            for(int j = 0; j < 4; j++){
                int idx = n*64 + tx*4 + j;
                float v = g_x[idx] + g_num[idx]*inv + acc[i][j] + cb[tx*4 + j];
                g_x[idx] = v;
                g_num[idx] = 0.f;
            }
        }
    } else {
        #pragma unroll
        for(int i = 0; i < 4; i++){
            int n = n0 + ty*4 + i;
            int b = batch[n];
            #pragma unroll
            for(int j = 0; j < 4; j++)
                atomicAdd(&g_pool[b*64 + tx*4 + j], acc[i][j] + bias[tx*4 + j]);
        }
    }
}

// ---------------- head -------------------------------------------------------------
__global__ void k_out(const float* __restrict__ oW, const float* __restrict__ ob,
                      float* __restrict__ out){
    __shared__ float p[64];
    int g = blockIdx.x, t = threadIdx.x;
    if(t < 64){
        float c = fmaxf(g_cnt[g], 1.f);
        p[t] = leaky(g_pool[g*64 + t] / c);
    }
    __syncthreads();
    float acc = ob[t];
    #pragma unroll 8
    for(int f = 0; f < 64; f++)
        acc = fmaf(p[f], oW[f*128 + t], acc);
    out[g*128 + t] = acc;
}

// ---------------- launch -------------------------------------------------------------
extern "C" void kernel_launch(void* const* d_in, const int* in_sizes, int n_in,
                              void* d_out, int out_size){
    const float* x    = (const float*)d_in[0];
    const int*   ei   = (const int*)  d_in[1];
    const float* ea   = (const float*)d_in[2];
    const int*   batch= (const int*)  d_in[3];
    const float* lns  = (const float*)d_in[4];
    const float* lnb  = (const float*)d_in[5];
    const float* W1   = (const float*)d_in[6];
    const float* b1   = (const float*)d_in[7];
    const float* W2   = (const float*)d_in[8];
    const float* b2   = (const float*)d_in[9];
    const float* root = (const float*)d_in[10];
    const float* cb   = (const float*)d_in[11];
    const float* dW   = (const float*)d_in[12];
    const float* db   = (const float*)d_in[13];
    const float* oW   = (const float*)d_in[14];
    const float* ob   = (const float*)d_in[15];
    float* out = (float*)d_out;

    k_init<<<(Nn*Dd + 255)/256, 256>>>(x);
    k_degcnt<<<(Ne + 255)/256, 256>>>(ei, batch);
    k_scan<<<1, 1024>>>();
    k_fill<<<(Ne + 255)/256, 256>>>(ei);
    k_prep_w2<<<(Ll*Hh*Dd*Dd + 255)/256, 256>>>(W2);

    for(int l = 0; l < Ll; l++){
        k_ln<<<Nn/8, 256>>>(lns + l*64, lnb + l*64);
        k_emlp<<<Ne/64, 256>>>(ea, W1 + (size_t)l*64*128, b1 + (size_t)l*128);
        k_nn64<<<Nn/64, 256>>>(b2 + (size_t)l*4096, nullptr, nullptr, nullptr, 0); // y2 = h@B2
        dim3 gq(Nn/128, Hh/8);
        k_q_mma<<<gq, 256>>>(l);
        k_msg2<<<Nn, 256>>>();
        k_nn64<<<Nn/64, 256>>>(root + (size_t)l*4096, nullptr, cb + (size_t)l*64, nullptr, 1);
    }

    k_nn64<<<Nn/64, 256>>>(dW, db, nullptr, batch, 2);  // dense + pool
    k_out<<<Gg, 128>>>(oW, ob, out);
}

// round 6
// speedup vs baseline: 1.8262x; 1.0699x over previous
#include <cuda_runtime.h>
#include <cuda_bf16.h>
#include <cuda_fp16.h>
#include <cstdint>

#define Nn 16384
#define Ne 65536
#define Dd 64
#define Hh 128
#define Ll 3
#define Gg 512
#define Oo 128

// ---------------- scratch -------------------------------------------------------
__device__ float g_x[Nn*Dd];
__device__ float g_h[Nn*Dd];
__device__ __nv_bfloat16 g_h_hi[Nn*Dd];
__device__ __nv_bfloat16 g_h_lo[Nn*Dd];
__device__ float g_y2[Nn*Dd];
__device__ float g_a[(size_t)Ne*Hh];
__device__ __half g_Q[(size_t)Nn*Hh*Dd];                 // [n][k][f], fp16, 256 MB
__device__ __nv_bfloat16 g_w2t_hi[(size_t)Ll*Hh*Dd*Dd]; // [l][k][f][d]
__device__ __nv_bfloat16 g_w2t_lo[(size_t)Ll*Hh*Dd*Dd];
__device__ __nv_bfloat16 g_w1t_hi[(size_t)Ll*Hh*Dd];    // [l][f=128][d=64]
__device__ __nv_bfloat16 g_w1t_lo[(size_t)Ll*Hh*Dd];
__device__ __nv_bfloat16 g_ea_hi[(size_t)Ne*Dd];
__device__ __nv_bfloat16 g_ea_lo[(size_t)Ne*Dd];
__device__ float g_num[Nn*Dd];
__device__ float g_deg[Nn];
__device__ float g_pool[Gg*Dd];
__device__ float g_cnt[Gg];
// CSR by src
__device__ int g_srccnt[Nn];
__device__ int g_cursor[Nn];
__device__ int g_rowptr[Nn + 1];
__device__ int g_edst[Ne];
__device__ int g_eidx[Ne];

__device__ __forceinline__ float leaky(float v){ return v > 0.f ? v : 0.01f*v; }

// ---------------- init -----------------------------------------------------------
__global__ void k_init(const float* __restrict__ x){
    int i = blockIdx.x*blockDim.x + threadIdx.x;
    if(i < Nn*Dd){ g_x[i] = x[i]; g_num[i] = 0.f; }
    if(i < Gg*Dd) g_pool[i] = 0.f;
    if(i < Nn){ g_deg[i] = 0.f; g_srccnt[i] = 0; g_cursor[i] = 0; }
    if(i < Gg)  g_cnt[i] = 0.f;
}

__global__ void k_degcnt(const int* __restrict__ ei, const int* __restrict__ batch){
    int i = blockIdx.x*blockDim.x + threadIdx.x;
    if(i < Ne){
        atomicAdd(&g_deg[ei[Ne + i]], 1.f);
        atomicAdd(&g_srccnt[ei[i]], 1);
    }
    if(i < Nn) atomicAdd(&g_cnt[batch[i]], 1.f);
}

// single-block exclusive scan of g_srccnt -> g_rowptr
__global__ void k_scan(){
    __shared__ int wsum[32];
    int t = threadIdx.x;
    int base = t*16;
    int c[16]; int s = 0;
    #pragma unroll
    for(int i = 0; i < 16; i++){ c[i] = g_srccnt[base + i]; s += c[i]; }
    int lane = t & 31, w = t >> 5;
    int v = s;
    #pragma unroll
    for(int o = 1; o < 32; o <<= 1){ int u = __shfl_up_sync(~0u, v, o); if(lane >= o) v += u; }
    if(lane == 31) wsum[w] = v;
    __syncthreads();
    if(w == 0){
        int x = wsum[lane];
        #pragma unroll
        for(int o = 1; o < 32; o <<= 1){ int u = __shfl_up_sync(~0u, x, o); if(lane >= o) x += u; }
        wsum[lane] = x;
    }
    __syncthreads();
    int run = v - s + (w > 0 ? wsum[w-1] : 0);
    #pragma unroll
    for(int i = 0; i < 16; i++){ g_rowptr[base + i] = run; run += c[i]; }
    if(t == 1023) g_rowptr[Nn] = run;
}

__global__ void k_fill(const int* __restrict__ ei){
    int e = blockIdx.x*blockDim.x + threadIdx.x;
    if(e >= Ne) return;
    int src = ei[e];
    int pos = g_rowptr[src] + atomicAdd(&g_cursor[src], 1);
    g_edst[pos] = ei[Ne + e];
    g_eidx[pos] = e;
}

// ---------------- W2 transpose + bf16 split: [l][k][d][f] -> [l][k][f][d] ---------
__global__ void k_prep_w2(const float* __restrict__ W2){
    int idx = blockIdx.x*blockDim.x + threadIdx.x;
    if(idx >= Ll*Hh*Dd*Dd) return;
    int lk = idx >> 12;
    int d = (idx >> 6) & 63;
    int f = idx & 63;
    float v = W2[idx];
    __nv_bfloat16 hi = __float2bfloat16(v);
    __nv_bfloat16 lo = __float2bfloat16(v - __bfloat162float(hi));
    size_t o = (size_t)lk*4096 + f*64 + d;
    g_w2t_hi[o] = hi;
    g_w2t_lo[o] = lo;
}

// ---------------- W1 transpose + split: [l][d=64][f=128] -> [l][f][d] -------------
__global__ void k_prep_w1(const float* __restrict__ W1){
    int idx = blockIdx.x*blockDim.x + threadIdx.x;
    if(idx >= Ll*Dd*Hh) return;
    int l = idx >> 13;
    int d = (idx >> 7) & 63;
    int f = idx & 127;
    float v = W1[idx];
    __nv_bfloat16 hi = __float2bfloat16(v);
    __nv_bfloat16 lo = __float2bfloat16(v - __bfloat162float(hi));
    size_t o = (size_t)l*Hh*Dd + f*64 + d;
    g_w1t_hi[o] = hi;
    g_w1t_lo[o] = lo;
}

// ---------------- edge_attr bf16 split (layer-invariant, once) --------------------
__global__ void k_prep_ea(const float* __restrict__ ea){
    int idx = blockIdx.x*blockDim.x + threadIdx.x;
    if(idx >= Ne*Dd) return;
    float v = ea[idx];
    __nv_bfloat16 hi = __float2bfloat16(v);
    g_ea_hi[idx] = hi;
    g_ea_lo[idx] = __float2bfloat16(v - __bfloat162float(hi));
}

// ---------------- h = leaky(LN(x)); also emit bf16 hi/lo --------------------------
__global__ void k_ln(const float* __restrict__ sc, const float* __restrict__ bi){
    int lane = threadIdx.x & 31, w = threadIdx.x >> 5;
    int n = blockIdx.x*8 + w;
    float v0 = g_x[n*64 + lane], v1 = g_x[n*64 + 32 + lane];
    float s = v0 + v1;
    #pragma unroll
    for(int o = 16; o; o >>= 1) s += __shfl_xor_sync(0xffffffffu, s, o);
    float mu = s * 0.015625f;
    float d0 = v0 - mu, d1 = v1 - mu;
    float q = d0*d0 + d1*d1;
    #pragma unroll
    for(int o = 16; o; o >>= 1) q += __shfl_xor_sync(0xffffffffu, q, o);
    float r = rsqrtf(q * 0.015625f + 1e-5f);
    float h0 = leaky(d0*r*sc[lane]      + bi[lane]);
    float h1 = leaky(d1*r*sc[32 + lane] + bi[32 + lane]);
    g_h[n*64 + lane]      = h0;
    g_h[n*64 + 32 + lane] = h1;
    __nv_bfloat16 h0h = __float2bfloat16(h0), h1h = __float2bfloat16(h1);
    g_h_hi[n*64 + lane]      = h0h;
    g_h_hi[n*64 + 32 + lane] = h1h;
    g_h_lo[n*64 + lane]      = __float2bfloat16(h0 - __bfloat162float(h0h));
    g_h_lo[n*64 + 32 + lane] = __float2bfloat16(h1 - __bfloat162float(h1h));
}

// ---------------- mma helper (fragment mapping VALIDATED in R5) --------------------
#define BPAD 72
__device__ __forceinline__ void mma_bf16(float* c, const uint32_t* a, uint32_t b0, uint32_t b1){
    asm volatile(
        "mma.sync.aligned.m16n8k16.row.col.f32.bf16.bf16.f32 "
        "{%0,%1,%2,%3}, {%4,%5,%6,%7}, {%8,%9}, {%0,%1,%2,%3};"
        : "+f"(c[0]), "+f"(c[1]), "+f"(c[2]), "+f"(c[3])
        : "r"(a[0]), "r"(a[1]), "r"(a[2]), "r"(a[3]), "r"(b0), "r"(b1));
}

// load A fragments (16 rows starting at m0, K=64, 4 k-steps) from hi/lo bf16 arrays
__device__ __forceinline__ void load_a_frags(const __nv_bfloat16* ph, const __nv_bfloat16* pl,
                                             int m0, int g, int tq,
                                             uint32_t ahi[4][4], uint32_t alo[4][4]){
    int r0 = (m0 + g)*64, r1 = (m0 + g + 8)*64;
    #pragma unroll
    for(int ks = 0; ks < 4; ks++){
        int c0 = ks*16 + 2*tq, c1 = c0 + 8;
        ahi[ks][0] = *(const uint32_t*)&ph[r0 + c0];
        ahi[ks][1] = *(const uint32_t*)&ph[r1 + c0];
        ahi[ks][2] = *(const uint32_t*)&ph[r0 + c1];
        ahi[ks][3] = *(const uint32_t*)&ph[r1 + c1];
        alo[ks][0] = *(const uint32_t*)&pl[r0 + c0];
        alo[ks][1] = *(const uint32_t*)&pl[r1 + c0];
        alo[ks][2] = *(const uint32_t*)&pl[r0 + c1];
        alo[ks][3] = *(const uint32_t*)&pl[r1 + c1];
    }
}

// ---------------- a = leaky(ea @ W1 + b1) via mma (3-term split) -------------------
// A = ea [128 e x 64 d], B = W1T [128 f x 64 d] (col-major for row.col), N=128.
__global__ __launch_bounds__(256) void k_emlp_mma(int layer, const float* __restrict__ b1l){
    __shared__ __align__(16) __nv_bfloat16 Bh[128*BPAD];
    __shared__ __align__(16) __nv_bfloat16 Bl[128*BPAD];
    const __nv_bfloat16* w1h = g_w1t_hi + (size_t)layer*Hh*Dd;
    const __nv_bfloat16* w1l = g_w1t_lo + (size_t)layer*Hh*Dd;
    int tid = threadIdx.x, w = tid >> 5, lane = tid & 31;
    int g = lane >> 2, tq = lane & 3;
    int e0 = blockIdx.x * 128;
    int m0 = e0 + w*16;

    uint32_t ahi[4][4], alo[4][4];
    load_a_frags(g_ea_hi, g_ea_lo, m0, g, tq, ahi, alo);

    // stage B: 128 rows(f) x 64(d) bf16 = 1024 uint4 per matrix, 4 per thread
    {
        const uint4* sh = (const uint4*)w1h;
        const uint4* sl = (const uint4*)w1l;
        #pragma unroll
        for(int i = 0; i < 4; i++){
            int idx = i*256 + tid;
            int f = idx >> 3, u = idx & 7;
            *(uint4*)&Bh[f*BPAD + u*8] = sh[idx];
            *(uint4*)&Bl[f*BPAD + u*8] = sl[idx];
        }
    }
    __syncthreads();

    float acc[16][4];
    #pragma unroll
    for(int j = 0; j < 16; j++)
        #pragma unroll
        for(int i = 0; i < 4; i++) acc[j][i] = 0.f;

    #pragma unroll
    for(int ks = 0; ks < 4; ks++){
        int cb0 = ks*16 + 2*tq, cb1 = cb0 + 8;
        #pragma unroll
        for(int j = 0; j < 16; j++){
            int row = (j*8 + g)*BPAD;
            uint32_t bh0 = *(const uint32_t*)&Bh[row + cb0];
            uint32_t bh1 = *(const uint32_t*)&Bh[row + cb1];
            uint32_t bl0 = *(const uint32_t*)&Bl[row + cb0];
            uint32_t bl1 = *(const uint32_t*)&Bl[row + cb1];
            mma_bf16(acc[j], ahi[ks], bh0, bh1);
            mma_bf16(acc[j], ahi[ks], bl0, bl1);
            mma_bf16(acc[j], alo[ks], bh0, bh1);
        }
    }

    // epilogue: bias + leaky; D rows m0+g / m0+g+8, cols c=j*8+2tq (+1)
    float* a0 = g_a + (size_t)(m0 + g)*128;
    float* a1 = g_a + (size_t)(m0 + g + 8)*128;
    #pragma unroll
    for(int j = 0; j < 16; j++){
        int c = j*8 + 2*tq;
        float2 bb = *(const float2*)&b1l[c];
        *(float2*)&a0[c] = make_float2(leaky(acc[j][0] + bb.x), leaky(acc[j][1] + bb.y));
        *(float2*)&a1[c] = make_float2(leaky(acc[j][2] + bb.x), leaky(acc[j][3] + bb.y));
    }
}

// ---------------- Q via mma (3-term split, fp32 accum, fp16 store) -----------------
__global__ __launch_bounds__(256) void k_q_mma(int layer){
    __shared__ __align__(16) __nv_bfloat16 Bh[64*BPAD];
    __shared__ __align__(16) __nv_bfloat16 Bl[64*BPAD];
    const __nv_bfloat16* w2h = g_w2t_hi + (size_t)layer*Hh*4096;
    const __nv_bfloat16* w2l = g_w2t_lo + (size_t)layer*Hh*4096;
    int tid = threadIdx.x, w = tid >> 5, lane = tid & 31;
    int g = lane >> 2, tq = lane & 3;
    int n0 = blockIdx.x * 128;
    int m0 = n0 + w*16;

    uint32_t ahi[4][4], alo[4][4];
    load_a_frags(g_h_hi, g_h_lo, m0, g, tq, ahi, alo);

    // prefetch B for kk=0 (2 uint4 per matrix per thread)
    int kbase = blockIdx.y*8;
    uint4 pf_h0, pf_h1, pf_l0, pf_l1;
    {
        const uint4* sh = (const uint4*)(w2h + (size_t)kbase*4096);
        const uint4* sl = (const uint4*)(w2l + (size_t)kbase*4096);
        pf_h0 = sh[tid]; pf_h1 = sh[256 + tid];
        pf_l0 = sl[tid]; pf_l1 = sl[256 + tid];
    }

    int f0 = tid >> 3,         u0 = tid & 7;
    int f1 = (256 + tid) >> 3, u1 = tid & 7;

    for(int kk = 0; kk < 8; kk++){
        int k = kbase + kk;
        __syncthreads();                       // prior mma done reading B
        *(uint4*)&Bh[f0*BPAD + u0*8] = pf_h0;
        *(uint4*)&Bh[f1*BPAD + u1*8] = pf_h1;
        *(uint4*)&Bl[f0*BPAD + u0*8] = pf_l0;
        *(uint4*)&Bl[f1*BPAD + u1*8] = pf_l1;
        if(kk < 7){                            // prefetch next while mma runs
            const uint4* sh = (const uint4*)(w2h + (size_t)(k + 1)*4096);
            const uint4* sl = (const uint4*)(w2l + (size_t)(k + 1)*4096);
            pf_h0 = sh[tid]; pf_h1 = sh[256 + tid];
            pf_l0 = sl[tid]; pf_l1 = sl[256 + tid];
        }
        __syncthreads();

        float acc[8][4];
        #pragma unroll
        for(int j = 0; j < 8; j++)
            #pragma unroll
            for(int i = 0; i < 4; i++) acc[j][i] = 0.f;

        #pragma unroll
        for(int ks = 0; ks < 4; ks++){
            int cb0 = ks*16 + 2*tq, cb1 = cb0 + 8;
            #pragma unroll
            for(int j = 0; j < 8; j++){
                int row = (j*8 + g)*BPAD;
                uint32_t bh0 = *(const uint32_t*)&Bh[row + cb0];
                uint32_t bh1 = *(const uint32_t*)&Bh[row + cb1];
                uint32_t bl0 = *(const uint32_t*)&Bl[row + cb0];
                uint32_t bl1 = *(const uint32_t*)&Bl[row + cb1];
                mma_bf16(acc[j], ahi[ks], bh0, bh1);
                mma_bf16(acc[j], ahi[ks], bl0, bl1);
                mma_bf16(acc[j], alo[ks], bh0, bh1);
            }
        }

        __half* q0 = g_Q + ((size_t)(m0 + g)*128 + k)*64;
        __half* q1 = g_Q + ((size_t)(m0 + g + 8)*128 + k)*64;
        #pragma unroll
        for(int j = 0; j < 8; j++){
            int c = j*8 + 2*tq;
            *(__half2*)&q0[c] = __floats2half2_rn(acc[j][0], acc[j][1]);
            *(__half2*)&q1[c] = __floats2half2_rn(acc[j][2], acc[j][3]);
        }
    }
}

// ---------------- messages: block per src node, fp16 Q staged to fp32 smem ---------
__global__ __launch_bounds__(256) void k_msg2(){
    __shared__ float Qs[128*64];
    __shared__ float as[4][128];
    __shared__ float y2s[64];
    int n = blockIdx.x;
    int beg = g_rowptr[n], end = g_rowptr[n+1];
    if(beg == end) return;
    int tid = threadIdx.x;
    // stage: 8192 halves = 1024 uint4; 4 per thread; convert to fp32
    const uint4* qsrc = (const uint4*)(g_Q + (size_t)n*8192);
    #pragma unroll
    for(int i = 0; i < 4; i++){
        int idx = i*256 + tid;
        uint4 v = qsrc[idx];
        const __half2* hp = (const __half2*)&v;
        float2 f0 = __half22float2(hp[0]);
        float2 f1 = __half22float2(hp[1]);
        float2 f2 = __half22float2(hp[2]);
        float2 f3 = __half22float2(hp[3]);
        float* dst = &Qs[idx*8];
        *(float4*)dst       = make_float4(f0.x, f0.y, f1.x, f1.y);
        *(float4*)(dst + 4) = make_float4(f2.x, f2.y, f3.x, f3.y);
    }
    if(tid < 64) y2s[tid] = g_y2[n*64 + tid];
    __syncthreads();
    int g = tid >> 6, f = tid & 63;
    for(int base = beg; base < end; base += 4){
        int j = base + g;
        int dst = 0;
        bool act = (j < end);
        if(act){
            dst = g_edst[j];
            int eid = g_eidx[j];
            as[g][f]      = g_a[(size_t)eid*128 + f];
            as[g][64 + f] = g_a[(size_t)eid*128 + 64 + f];
        }
        __syncthreads();
        if(act){
            float acc = y2s[f];
            #pragma unroll 16
            for(int k = 0; k < 128; k++)
                acc = fmaf(as[g][k], Qs[k*64 + f], acc);
            atomicAdd(&g_num[dst*64 + f], acc);
        }
        __syncthreads();
    }
}

// ---------------- shared 64x64 small GEMM with three epilogues ---------------------
__global__ __launch_bounds__(256) void k_nn64(const float* __restrict__ B,
                                              const float* __restrict__ bias,
                                              const float* __restrict__ cb,
                                              const int* __restrict__ batch,
                                              int mode){
    __shared__ float As[64][64];
    __shared__ float Bs[64][64];
    const float* A = (mode == 2) ? g_x : g_h;
    int tid = threadIdx.x;
    int n0 = blockIdx.x * 64;
    #pragma unroll
    for(int i = 0; i < 4; i++){
        int idx = i*256 + tid; int m = idx >> 4, d = (idx & 15) * 4;
        *(float4*)&As[m][d] = *(const float4*)&A[(size_t)(n0 + m)*64 + d];
        *(float4*)&Bs[m][d] = *(const float4*)&B[(size_t)m*64 + d];
    }
    __syncthreads();
    int tx = tid & 15, ty = tid >> 4;
    float acc[4][4];
    #pragma unroll
    for(int i = 0; i < 4; i++)
        #pragma unroll
        for(int j = 0; j < 4; j++) acc[i][j] = 0.f;

    #pragma unroll 4
    for(int d4 = 0; d4 < 64; d4 += 4){
        float4 a[4];
        #pragma unroll
        for(int i = 0; i < 4; i++) a[i] = *(float4*)&As[ty*4 + i][d4];
        #pragma unroll
        for(int dd = 0; dd < 4; dd++){
            float4 bv = *(float4*)&Bs[d4 + dd][tx*4];
            #pragma unroll
            for(int i = 0; i < 4; i++){
                float av = (dd==0)?a[i].x:(dd==1)?a[i].y:(dd==2)?a[i].z:a[i].w;
                acc[i][0] = fmaf(av, bv.x, acc[i][0]);
                acc[i][1] = fmaf(av, bv.y, acc[i][1]);
                acc[i][2] = fmaf(av, bv.z, acc[i][2]);
                acc[i][3] = fmaf(av, bv.w, acc[i][3]);
            }
        }
    }
    if(mode == 0){
        #pragma unroll
        for(int i = 0; i < 4; i++){
            float4 o; o.x = acc[i][0]; o.y = acc[i][1]; o.z = acc[i][2]; o.w = acc[i][3];
            *(float4*)&g_y2[(size_t)(n0 + ty*4 + i)*64 + tx*4] = o;
        }
    } else if(mode == 1){
        #pragma unroll
        for(int i = 0; i < 4; i++){
            int n = n0 + ty*4 + i;
            float inv = 1.f / fmaxf(g_deg[n], 1.f);
            #pragma unroll
            for(int j = 0; j < 4; j++){
                int idx = n*64 + tx*4 + j;
                float v = g_x[idx] + g_num[idx]*inv + acc[i][j] + cb[tx*4 + j];
                g_x[idx] = v;
                g_num[idx] = 0.f;
            }
        }
    } else {
        #pragma unroll
        for(int i = 0; i < 4; i++){
            int n = n0 + ty*4 + i;
            int b = batch[n];
            #pragma unroll
            for(int j = 0; j < 4; j++)
                atomicAdd(&g_pool[b*64 + tx*4 + j], acc[i][j] + bias[tx*4 + j]);
        }
    }
}

// ---------------- head -------------------------------------------------------------
__global__ void k_out(const float* __restrict__ oW, const float* __restrict__ ob,
                      float* __restrict__ out){
    __shared__ float p[64];
    int g = blockIdx.x, t = threadIdx.x;
    if(t < 64){
        float c = fmaxf(g_cnt[g], 1.f);
        p[t] = leaky(g_pool[g*64 + t] / c);
    }
    __syncthreads();
    float acc = ob[t];
    #pragma unroll 8
    for(int f = 0; f < 64; f++)
        acc = fmaf(p[f], oW[f*128 + t], acc);
    out[g*128 + t] = acc;
}

// ---------------- launch -------------------------------------------------------------
extern "C" void kernel_launch(void* const* d_in, const int* in_sizes, int n_in,
                              void* d_out, int out_size){
    const float* x    = (const float*)d_in[0];
    const int*   ei   = (const int*)  d_in[1];
    const float* ea   = (const float*)d_in[2];
    const int*   batch= (const int*)  d_in[3];
    const float* lns  = (const float*)d_in[4];
    const float* lnb  = (const float*)d_in[5];
    const float* W1   = (const float*)d_in[6];
    const float* b1   = (const float*)d_in[7];
    const float* W2   = (const float*)d_in[8];
    const float* b2   = (const float*)d_in[9];
    const float* root = (const float*)d_in[10];
    const float* cb   = (const float*)d_in[11];
    const float* dW   = (const float*)d_in[12];
    const float* db   = (const float*)d_in[13];
    const float* oW   = (const float*)d_in[14];
    const float* ob   = (const float*)d_in[15];
    float* out = (float*)d_out;

    k_init<<<(Nn*Dd + 255)/256, 256>>>(x);
    k_degcnt<<<(Ne + 255)/256, 256>>>(ei, batch);
    k_scan<<<1, 1024>>>();
    k_fill<<<(Ne + 255)/256, 256>>>(ei);
    k_prep_w2<<<(Ll*Hh*Dd*Dd + 255)/256, 256>>>(W2);
    k_prep_w1<<<(Ll*Dd*Hh + 255)/256, 256>>>(W1);
    k_prep_ea<<<(Ne*Dd + 255)/256, 256>>>(ea);

    for(int l = 0; l < Ll; l++){
        k_ln<<<Nn/8, 256>>>(lns + l*64, lnb + l*64);
        k_emlp_mma<<<Ne/128, 256>>>(l, b1 + (size_t)l*128);
        k_nn64<<<Nn/64, 256>>>(b2 + (size_t)l*4096, nullptr, nullptr, nullptr, 0); // y2 = h@B2
        dim3 gq(Nn/128, Hh/8);
        k_q_mma<<<gq, 256>>>(l);
        k_msg2<<<Nn, 256>>>();
        k_nn64<<<Nn/64, 256>>>(root + (size_t)l*4096, nullptr, cb + (size_t)l*64, nullptr, 1);
    }

    k_nn64<<<Nn/64, 256>>>(dW, db, nullptr, batch, 2);  // dense + pool
    k_out<<<Gg, 128>>>(oW, ob, out);
}